// round 15
// baseline (speedup 1.0000x reference)
#include <cuda_runtime.h>
#include <math.h>
#include <stdint.h>

#define D   32
#define BB  8192
#define TT  256
#define MT  64      // rows per CTA -> 128 CTAs

// smem byte offsets
#define B_A1   0        // z state fp32 [64 batch][36]     9216
#define B_H1   9216     // H1 fp32 [64 batch][68]          17408
#define B_H2   26624    // H2 fp32 [64 batch][68]          17408
#define B_TS   44032    // ts fp32 [256]                   1024
#define SMEM_BYTES 45056

__device__ __forceinline__ uint32_t f2tf(float x){
    uint32_t r; asm("cvt.rna.tf32.f32 %0, %1;" : "=r"(r) : "f"(x)); return r;
}
__device__ __forceinline__ float tanha(float x){
    float y; asm("tanh.approx.f32 %0, %1;" : "=f"(y) : "f"(x)); return y;
}
__device__ __forceinline__ void mma8(float d[4],
    uint32_t a0, uint32_t a1, uint32_t a2, uint32_t a3,
    uint32_t b0, uint32_t b1){
    asm volatile("mma.sync.aligned.m16n8k8.row.col.f32.tf32.tf32.f32 "
        "{%0,%1,%2,%3}, {%4,%5,%6,%7}, {%8,%9}, {%0,%1,%2,%3};"
        : "+f"(d[0]), "+f"(d[1]), "+f"(d[2]), "+f"(d[3])
        : "r"(a0), "r"(a1), "r"(a2), "r"(a3), "r"(b0), "r"(b1));
}
#define SPLIT(x, hi, lo) { hi = f2tf(x); lo = f2tf((x) - __uint_as_float(hi)); }

__global__ __launch_bounds__(256, 1)
void sde_mma(const float* __restrict__ z0, const float* __restrict__ ts,
             const float* __restrict__ dW,
             const float* __restrict__ W1, const float* __restrict__ b1,
             const float* __restrict__ W2, const float* __restrict__ b2,
             const float* __restrict__ W3, const float* __restrict__ b3,
             const float* __restrict__ logstd, float* __restrict__ out)
{
    extern __shared__ char smem[];
    float* A1  = (float*)(smem + B_A1);   // [batch][36] feature-in-row
    float* H1  = (float*)(smem + B_H1);   // [batch][68]
    float* H2  = (float*)(smem + B_H2);   // [batch][68]
    float* sTs = (float*)(smem + B_TS);

    const int tid  = threadIdx.x;
    const int w    = tid >> 5;
    const int lane = tid & 31;
    const int g    = lane >> 2;     // 0..7
    const int tig  = lane & 3;      // 0..3
    // GEMM1/2 warp layout: mt = out m16 tile (0..3), bh = batch half (0..1)
    const int mt   = w & 3;
    const int bh   = w >> 2;
    // GEMM3 warp layout: mt3 = out m16 tile (0..1), bq = batch quarter (0..3)
    const int mt3  = w & 1;
    const int bq   = w >> 1;
    const int base = blockIdx.x * MT;

    // ---- stage z0 -> A1, ts, out[0] ----
    for (int i = tid; i < 64*32; i += 256){
        int r = i >> 5, c = i & 31;
        A1[r*36 + c] = z0[(size_t)(base + r)*D + c];
    }
    sTs[tid] = ts[tid];
    for (int i = tid; i < MT*D/2; i += 256)
        ((float2*)out)[(size_t)base*(D/2) + i] = ((const float2*)z0)[(size_t)base*(D/2) + i];

    // ---- hoist weights into registers as A-fragments (Y^T = W^T X^T) ----
    // A[m=out][k=in] = W[k][m];  a0=(g,tig) a1=(g+8,tig) a2=(g,tig+4) a3=(g+8,tig+4)
    uint32_t w1h[4][4], w1l[4][4];      // GEMM1: out tile mt, k 0..31 (W1 rows 1..32)
    {
        const int m0 = mt*16 + g;
        #pragma unroll
        for (int kt = 0; kt < 4; kt++){
            int k0 = kt*8 + tig;
            float a0 = W1[(k0+1)*64 + m0],     a1 = W1[(k0+1)*64 + m0+8];
            float a2 = W1[(k0+5)*64 + m0],     a3 = W1[(k0+5)*64 + m0+8];
            SPLIT(a0, w1h[kt][0], w1l[kt][0]); SPLIT(a1, w1h[kt][1], w1l[kt][1]);
            SPLIT(a2, w1h[kt][2], w1l[kt][2]); SPLIT(a3, w1h[kt][3], w1l[kt][3]);
        }
    }
    uint32_t w2h[8][4], w2l[8][4];      // GEMM2
    {
        const int m0 = mt*16 + g;
        #pragma unroll
        for (int kt = 0; kt < 8; kt++){
            int k0 = kt*8 + tig;
            float a0 = W2[k0*64 + m0],     a1 = W2[k0*64 + m0+8];
            float a2 = W2[(k0+4)*64 + m0], a3 = W2[(k0+4)*64 + m0+8];
            SPLIT(a0, w2h[kt][0], w2l[kt][0]); SPLIT(a1, w2h[kt][1], w2l[kt][1]);
            SPLIT(a2, w2h[kt][2], w2l[kt][2]); SPLIT(a3, w2h[kt][3], w2l[kt][3]);
        }
    }
    uint32_t w3h[8][4], w3l[8][4];      // GEMM3: out tile mt3 (32 cols)
    {
        const int m0 = mt3*16 + g;
        #pragma unroll
        for (int kt = 0; kt < 8; kt++){
            int k0 = kt*8 + tig;
            float a0 = W3[k0*32 + m0],     a1 = W3[k0*32 + m0+8];
            float a2 = W3[(k0+4)*32 + m0], a3 = W3[(k0+4)*32 + m0+8];
            SPLIT(a0, w3h[kt][0], w3l[kt][0]); SPLIT(a1, w3h[kt][1], w3l[kt][1]);
            SPLIT(a2, w3h[kt][2], w3l[kt][2]); SPLIT(a3, w3h[kt][3], w3l[kt][3]);
        }
    }
    // out-row-indexed constants
    const float b1g0 = b1[mt*16 + g],   b1g1 = b1[mt*16 + 8 + g];
    const float w10g0 = W1[mt*16 + g],  w10g1 = W1[mt*16 + 8 + g];   // W1 t-row
    const float b2g0 = b2[mt*16 + g],   b2g1 = b2[mt*16 + 8 + g];
    const float b3g0 = b3[mt3*16 + g],  b3g1 = b3[mt3*16 + 8 + g];
    const float sd0  = expf(logstd[mt3*16 + g]), sd1 = expf(logstd[mt3*16 + 8 + g]);
    __syncthreads();

    // ==================== time loop ====================
    for (int t = 0; t < TT-1; ++t){
        const float tc  = sTs[t];
        const float dtv = sTs[t+1] - tc;
        const float sq  = sqrtf(dtv);

        // prefetch noise for EM update: (m,n) per GEMM3 c-frag
        float dwv[2][4];
        #pragma unroll
        for (int nt = 0; nt < 2; nt++){
            const int n0 = bq*16 + nt*8 + 2*tig;
            const int m0 = mt3*16 + g;
            const float* dp = &dW[((size_t)t*BB + base)*D];
            dwv[nt][0] = dp[(size_t)n0*D + m0];
            dwv[nt][1] = dp[(size_t)(n0+1)*D + m0];
            dwv[nt][2] = dp[(size_t)n0*D + m0 + 8];
            dwv[nt][3] = dp[(size_t)(n0+1)*D + m0 + 8];
        }

        // ---------- GEMM1: H1^T = W1^T[.,1:33] z^T  (t folded into init) ----------
        {
            float d1[4][4];
            {
                float i0 = fmaf(tc, w10g0, b1g0);
                float i1 = fmaf(tc, w10g1, b1g1);
                #pragma unroll
                for (int nt = 0; nt < 4; nt++){
                    d1[nt][0] = i0; d1[nt][1] = i0; d1[nt][2] = i1; d1[nt][3] = i1;
                }
            }
            #pragma unroll
            for (int kt = 0; kt < 4; kt++){
                #pragma unroll
                for (int nt = 0; nt < 4; nt++){
                    const float* xp = A1 + (bh*32 + nt*8 + g)*36 + kt*8 + tig;
                    uint32_t b0 = f2tf(xp[0]), b1r = f2tf(xp[4]);
                    mma8(d1[nt], w1h[kt][0], w1h[kt][1], w1h[kt][2], w1h[kt][3], b0, b1r);
                    mma8(d1[nt], w1l[kt][0], w1l[kt][1], w1l[kt][2], w1l[kt][3], b0, b1r);
                }
            }
            const int m0 = mt*16 + g;
            #pragma unroll
            for (int nt = 0; nt < 4; nt++){
                const int n0 = bh*32 + nt*8 + 2*tig;
                H1[n0*68 + m0]         = tanha(d1[nt][0]);
                H1[(n0+1)*68 + m0]     = tanha(d1[nt][1]);
                H1[n0*68 + m0 + 8]     = tanha(d1[nt][2]);
                H1[(n0+1)*68 + m0 + 8] = tanha(d1[nt][3]);
            }
        }
        __syncthreads();

        // ---------- GEMM2: H2^T = W2^T H1^T ----------
        {
            float d2[4][4];
            #pragma unroll
            for (int nt = 0; nt < 4; nt++){
                d2[nt][0] = b2g0; d2[nt][1] = b2g0; d2[nt][2] = b2g1; d2[nt][3] = b2g1;
            }
            #pragma unroll
            for (int kt = 0; kt < 8; kt++){
                #pragma unroll
                for (int nt = 0; nt < 4; nt++){
                    const float* xp = H1 + (bh*32 + nt*8 + g)*68 + kt*8 + tig;
                    uint32_t b0 = f2tf(xp[0]), b1r = f2tf(xp[4]);
                    mma8(d2[nt], w2h[kt][0], w2h[kt][1], w2h[kt][2], w2h[kt][3], b0, b1r);
                    mma8(d2[nt], w2l[kt][0], w2l[kt][1], w2l[kt][2], w2l[kt][3], b0, b1r);
                }
            }
            const int m0 = mt*16 + g;
            #pragma unroll
            for (int nt = 0; nt < 4; nt++){
                const int n0 = bh*32 + nt*8 + 2*tig;
                H2[n0*68 + m0]         = tanha(d2[nt][0]);
                H2[(n0+1)*68 + m0]     = tanha(d2[nt][1]);
                H2[n0*68 + m0 + 8]     = tanha(d2[nt][2]);
                H2[(n0+1)*68 + m0 + 8] = tanha(d2[nt][3]);
            }
        }
        __syncthreads();

        // ---------- GEMM3: F^T = W3^T H2^T + fused Euler-Maruyama ----------
        {
            float d3[2][4];
            #pragma unroll
            for (int nt = 0; nt < 2; nt++){
                d3[nt][0] = b3g0; d3[nt][1] = b3g0; d3[nt][2] = b3g1; d3[nt][3] = b3g1;
            }
            #pragma unroll
            for (int kt = 0; kt < 8; kt++){
                #pragma unroll
                for (int nt = 0; nt < 2; nt++){
                    const float* xp = H2 + (bq*16 + nt*8 + g)*68 + kt*8 + tig;
                    uint32_t b0 = f2tf(xp[0]), b1r = f2tf(xp[4]);
                    mma8(d3[nt], w3h[kt][0], w3h[kt][1], w3h[kt][2], w3h[kt][3], b0, b1r);
                    mma8(d3[nt], w3l[kt][0], w3l[kt][1], w3l[kt][2], w3l[kt][3], b0, b1r);
                }
            }
            const int m0 = mt3*16 + g;
            const float s0 = sd0 * sq, s1 = sd1 * sq;
            float* op = &out[((size_t)(t+1)*BB + base)*D];
            #pragma unroll
            for (int nt = 0; nt < 2; nt++){
                const int n0 = bq*16 + nt*8 + 2*tig;
                float zn;
                zn = fmaf(d3[nt][0], dtv, fmaf(s0, dwv[nt][0], A1[n0*36 + m0]));
                A1[n0*36 + m0] = zn;         op[(size_t)n0*D + m0] = zn;
                zn = fmaf(d3[nt][1], dtv, fmaf(s0, dwv[nt][1], A1[(n0+1)*36 + m0]));
                A1[(n0+1)*36 + m0] = zn;     op[(size_t)(n0+1)*D + m0] = zn;
                zn = fmaf(d3[nt][2], dtv, fmaf(s1, dwv[nt][2], A1[n0*36 + m0 + 8]));
                A1[n0*36 + m0 + 8] = zn;     op[(size_t)n0*D + m0 + 8] = zn;
                zn = fmaf(d3[nt][3], dtv, fmaf(s1, dwv[nt][3], A1[(n0+1)*36 + m0 + 8]));
                A1[(n0+1)*36 + m0 + 8] = zn; op[(size_t)(n0+1)*D + m0 + 8] = zn;
            }
        }
        __syncthreads();
    }
}

extern "C" void kernel_launch(void* const* d_in, const int* in_sizes, int n_in,
                              void* d_out, int out_size)
{
    (void)in_sizes; (void)n_in; (void)out_size;
    const float* z0     = (const float*)d_in[0];
    const float* ts     = (const float*)d_in[1];
    const float* dW     = (const float*)d_in[2];
    const float* W1     = (const float*)d_in[3];
    const float* b1     = (const float*)d_in[4];
    const float* W2     = (const float*)d_in[5];
    const float* b2     = (const float*)d_in[6];
    const float* W3     = (const float*)d_in[7];
    const float* b3     = (const float*)d_in[8];
    const float* logstd = (const float*)d_in[9];
    float* out = (float*)d_out;

    static bool attr_set = false;  // idempotent attribute; not a work guard
    if (!attr_set) {
        cudaFuncSetAttribute(sde_mma, cudaFuncAttributeMaxDynamicSharedMemorySize,
                             SMEM_BYTES);
        attr_set = true;
    }

    sde_mma<<<BB / MT, 256, SMEM_BYTES>>>(
        z0, ts, dW, W1, b1, W2, b2, W3, b3, logstd, out);
}